// round 6
// baseline (speedup 1.0000x reference)
#include <cuda_runtime.h>
#include <cuda_bf16.h>
#include <cuda_fp16.h>
#include <cstdint>

#define INF   128
#define HIDF  256
#define OUTF  64
#define N1C   100000
#define N2C   25000
#define E0C   1600000
#define E1C   400000

// ======================= PTX helpers =======================
__device__ __forceinline__ uint32_t smem_to_u32(const void* smem_ptr) {
    uint32_t addr;
    asm("{ .reg .u64 tmp; cvta.to.shared.u64 tmp, %1; cvt.u32.u64 %0, tmp; }"
        : "=r"(addr) : "l"(smem_ptr));
    return addr;
}
#define CP_ASYNC16(dst, src) \
    asm volatile("cp.async.cg.shared.global [%0], [%1], 16;" :: "r"(dst), "l"(src))
#define CP_COMMIT() asm volatile("cp.async.commit_group;" ::: "memory")
#define CP_WAIT(n)  asm volatile("cp.async.wait_group %0;" :: "n"(n) : "memory")
#define LDSM4(r, addr) \
    asm volatile("ldmatrix.sync.aligned.m8n8.x4.shared.b16 {%0,%1,%2,%3}, [%4];" \
        : "=r"((r)[0]), "=r"((r)[1]), "=r"((r)[2]), "=r"((r)[3]) : "r"(addr))
#define MMA16816H(d, a, b) \
    asm volatile("mma.sync.aligned.m16n8k16.row.col.f32.f16.f16.f32 " \
        "{%0,%1,%2,%3}, {%4,%5,%6,%7}, {%8,%9}, {%0,%1,%2,%3};" \
        : "+f"((d)[0]), "+f"((d)[1]), "+f"((d)[2]), "+f"((d)[3]) \
        : "r"((a)[0]), "r"((a)[1]), "r"((a)[2]), "r"((a)[3]), \
          "r"((b)[0]), "r"((b)[1]))

__device__ __forceinline__ uint32_t pack2h(float a, float b) {
    __half2 p = __floats2half2_rn(a, b);
    return *reinterpret_cast<uint32_t*>(&p);
}
__device__ __forceinline__ float toh(float x) {
    return __half2float(__float2half_rn(x));
}

// ======================= device scratch =======================
__device__ __align__(16) float g_An[(size_t)N1C * INF];
__device__ __align__(16) float g_At[(size_t)N1C * INF];
__device__ __align__(16) float g_X1[(size_t)N1C * HIDF];
__device__ __align__(16) float g_Ag1[(size_t)N2C * HIDF];
__device__ int g_cnt0[N1C];
__device__ int g_off0[N1C + 1];
__device__ int g_cur0[N1C];
__device__ int g_es0[E0C];
__device__ int g_cnt1[N2C];
__device__ int g_off1[N2C + 1];
__device__ int g_cur1[N2C];
__device__ int g_es1[E1C];
#define NB0 ((N1C + 511) / 512)
#define NB1 ((N2C + 511) / 512)
__device__ unsigned long long g_lb[NB0 + NB1];              // lookback states
__device__ __align__(128) __half g_Bh[256 * 512];           // [N=256][K=512] combined W fp16
__device__ __align__(16) uint32_t g_W2f[64 * 512 / 2];      // W2 fp16, mma fragment order
__device__ float g_bA[HIDF];
__device__ float g_bB[HIDF];

// ======================= fused zero + weight prep =======================
#define ZB  489
#define WCB 512
#define W2B 128
__global__ void zero_prep_kernel(
    const float* __restrict__ Wl0, const float* __restrict__ Wr0,
    const float* __restrict__ b0,
    const float* __restrict__ Wl1, const float* __restrict__ Wr1,
    const float* __restrict__ b1,
    const float* __restrict__ Wl2, const float* __restrict__ Wr2) {
    int b = blockIdx.x, t = threadIdx.x;
    if (b < ZB) {
        int i = b * 256 + t;
        if (i < N1C) g_cnt0[i] = 0;
        else if (i < N1C + N2C) g_cnt1[i - N1C] = 0;
    } else if (b < ZB + WCB) {
        int idx = (b - ZB) * 256 + t;
        int i = idx >> 8;                  // K 0..511
        int j = idx & 255;                 // N 0..255
        int blk = i >> 7;
        int il = i & 127;
        const float* M1 = (blk == 0 || blk == 2) ? Wl0 : Wr0;
        const float* M2 = (blk < 2) ? Wl1 : Wr1;
        float s = 0.f;
        #pragma unroll 8
        for (int k = 0; k < 256; k++) s = fmaf(M1[il * 256 + k], M2[k * 256 + j], s);
        g_Bh[j * 512 + i] = __float2half_rn(s);
    } else if (b < ZB + WCB + W2B) {
        int e = (b - ZB - WCB) * 256 + t;
        int n = e & 63, k = e >> 6;
        float s = (k < 256) ? Wl2[k * 64 + n] : Wr2[(k - 256) * 64 + n];
        int k16 = k >> 4, nt = n >> 3, gid = n & 7;
        int kk = k & 15, reg = kk >> 3, tig = (kk & 7) >> 1, half = kk & 1;
        int u = ((k16 * 8 + nt) * 32 + gid * 4 + tig) * 2 + reg;
        reinterpret_cast<__half*>(g_W2f)[u * 2 + half] = __float2half_rn(s);
    } else {
        int j = t;
        float sa = 0.f, sb = 0.f;
        for (int k = 0; k < 256; k++) {
            sa = fmaf(b0[k], Wl1[k * 256 + j], sa);
            sb = fmaf(b0[k], Wr1[k * 256 + j], sb);
        }
        g_bA[j] = sa;
        g_bB[j] = sb + b1[j];
        if (t < NB0 + NB1) g_lb[t] = 0ull;
    }
}

// ======================= bookkeeping =======================
__global__ void countAll_kernel(const int* __restrict__ d0, const int* __restrict__ d1,
                                int e0, int e1) {
    int i = blockIdx.x * blockDim.x + threadIdx.x;
    if (i < e0) atomicAdd(&g_cnt0[d0[i]], 1);
    else if (i - e0 < e1) atomicAdd(&g_cnt1[d1[i - e0]], 1);
}
__global__ void scatterAll_kernel(const int* __restrict__ s0, const int* __restrict__ d0,
                                  const int* __restrict__ s1, const int* __restrict__ d1,
                                  int e0, int e1) {
    int i = blockIdx.x * blockDim.x + threadIdx.x;
    if (i < e0) {
        int p = atomicAdd(&g_cur0[d0[i]], 1);
        g_es0[p] = s0[i];
    } else if (i - e0 < e1) {
        int j = i - e0;
        int p = atomicAdd(&g_cur1[d1[j]], 1);
        g_es1[p] = s1[j];
    }
}

// Single-kernel decoupled-lookback scan for both levels.
__global__ void scanLB_kernel() {
    int b = blockIdx.x;
    int level = (b < NB0) ? 0 : 1;
    int bb = level ? (b - NB0) : b;
    const int* cnt = level ? g_cnt1 : g_cnt0;
    int* off = level ? g_off1 : g_off0;
    int* cur = level ? g_cur1 : g_cur0;
    int n = level ? N2C : N1C;
    unsigned long long* st = g_lb + (level ? NB0 : 0);

    __shared__ int ws[8];
    __shared__ int sbase;
    int t = threadIdx.x;
    int i0 = bb * 512 + t * 2;
    int c0 = (i0 < n) ? cnt[i0] : 0;
    int c1 = (i0 + 1 < n) ? cnt[i0 + 1] : 0;
    int s = c0 + c1;
    int lane = t & 31, w = t >> 5;
    int incl = s;
    #pragma unroll
    for (int o = 1; o < 32; o <<= 1) {
        int x = __shfl_up_sync(0xffffffffu, incl, o);
        if (lane >= o) incl += x;
    }
    if (lane == 31) ws[w] = incl;
    __syncthreads();
    if (t == 0) {
        int run = 0;
        #pragma unroll
        for (int i = 0; i < 8; i++) { int tm = ws[i]; ws[i] = run; run += tm; }
        int total = run;
        if (bb == 0) {
            atomicExch(&st[0], (2ull << 62) | (unsigned long long)(unsigned)total);
            sbase = 0;
        } else {
            atomicExch(&st[bb], (1ull << 62) | (unsigned long long)(unsigned)total);
            long long runp = 0;
            int p = bb - 1;
            while (true) {
                unsigned long long v = atomicAdd(&st[p], 0ull);
                unsigned long long f = v >> 62;
                if (f == 2ull) { runp += (unsigned)v; break; }
                if (f == 1ull) { runp += (unsigned)v; p--; }
            }
            atomicExch(&st[bb], (2ull << 62) | (unsigned long long)(unsigned)(runp + total));
            sbase = (int)runp;
        }
    }
    __syncthreads();
    int excl = sbase + (incl - s + ws[w]);
    if (i0 < n) { off[i0] = excl; cur[i0] = excl; }
    if (i0 + 1 < n) { off[i0 + 1] = excl + c0; cur[i0 + 1] = excl + c0; }
    if (i0 == n - 1) off[n] = excl + c0;
    else if (i0 + 1 == n - 1) off[n] = excl + c0 + c1;
}

// ======================= aggregation =======================
__global__ __launch_bounds__(256) void agg0_kernel(const float* __restrict__ xn,
                                                   const float* __restrict__ xt) {
    int w = threadIdx.x >> 5, lane = threadIdx.x & 31;
    int d = blockIdx.x * 4 + (w >> 1);
    if (d >= N1C) return;
    const float* src = (w & 1) ? xt : xn;
    float* dstp = (w & 1) ? g_At : g_An;
    int b = g_off0[d], e = g_off0[d + 1];
    float4 acc = make_float4(0.f, 0.f, 0.f, 0.f);
    int i = b;
    for (; i + 3 < e; i += 4) {
        int s0 = g_es0[i], s1 = g_es0[i + 1], s2 = g_es0[i + 2], s3 = g_es0[i + 3];
        float4 v0 = __ldg(reinterpret_cast<const float4*>(src + (size_t)s0 * INF) + lane);
        float4 v1 = __ldg(reinterpret_cast<const float4*>(src + (size_t)s1 * INF) + lane);
        float4 v2 = __ldg(reinterpret_cast<const float4*>(src + (size_t)s2 * INF) + lane);
        float4 v3 = __ldg(reinterpret_cast<const float4*>(src + (size_t)s3 * INF) + lane);
        acc.x += (v0.x + v1.x) + (v2.x + v3.x);
        acc.y += (v0.y + v1.y) + (v2.y + v3.y);
        acc.z += (v0.z + v1.z) + (v2.z + v3.z);
        acc.w += (v0.w + v1.w) + (v2.w + v3.w);
    }
    for (; i < e; i++) {
        int s0 = g_es0[i];
        float4 v0 = __ldg(reinterpret_cast<const float4*>(src + (size_t)s0 * INF) + lane);
        acc.x += v0.x; acc.y += v0.y; acc.z += v0.z; acc.w += v0.w;
    }
    float inv = (e > b) ? 1.f / (float)(e - b) : 0.f;
    acc.x *= inv; acc.y *= inv; acc.z *= inv; acc.w *= inv;
    reinterpret_cast<float4*>(dstp + (size_t)d * INF)[lane] = acc;
}

__global__ __launch_bounds__(256) void agg1_kernel() {
    int w = threadIdx.x >> 5, lane = threadIdx.x & 31;
    int d = blockIdx.x * 4 + (w >> 1);
    if (d >= N2C) return;
    int colb = (w & 1) * 128;
    int b = g_off1[d], e = g_off1[d + 1];
    float4 acc = make_float4(0.f, 0.f, 0.f, 0.f);
    int i = b;
    for (; i + 1 < e; i += 2) {
        int s0 = g_es1[i], s1 = g_es1[i + 1];
        float4 v0 = __ldg(reinterpret_cast<const float4*>(g_X1 + (size_t)s0 * HIDF + colb) + lane);
        float4 v1 = __ldg(reinterpret_cast<const float4*>(g_X1 + (size_t)s1 * HIDF + colb) + lane);
        acc.x += v0.x + v1.x; acc.y += v0.y + v1.y;
        acc.z += v0.z + v1.z; acc.w += v0.w + v1.w;
    }
    if (i < e) {
        int s0 = g_es1[i];
        float4 v0 = __ldg(reinterpret_cast<const float4*>(g_X1 + (size_t)s0 * HIDF + colb) + lane);
        acc.x += v0.x; acc.y += v0.y; acc.z += v0.z; acc.w += v0.w;
    }
    float inv = (e > b) ? 1.f / (float)(e - b) : 0.f;
    acc.x *= inv; acc.y *= inv; acc.z *= inv; acc.w *= inv;
    reinterpret_cast<float4*>(g_Ag1 + (size_t)d * HIDF + colb)[lane] = acc;
}

// ======================= HMMA fused layer-0+1 GEMM (fp16 2-term split) ================
// X1 = relu([A_n|A_t|xn_t|xt_t](K=512) @ Bh(512x256,fp16) + bias)
// D = Ahi@B + Alo@B; A split fp16 hi/lo (exact to 2^-24), B single fp16.
// CTA 128x128, 8 warps (warp tile 32x64), BK=32, double buffered; rows padded to 80B.
#define G1_AHI     0
#define G1_ALO     10240
#define G1_BH      20480
#define G1_STAGE   30720
#define GEMM1_SMEM (2 * G1_STAGE)

__global__ __launch_bounds__(256, 1) void gemm1_mma_kernel(const float* __restrict__ xn,
                                                           const float* __restrict__ xt,
                                                           int M) {
    extern __shared__ char smem[];
    const uint32_t smem_u = smem_to_u32(smem);
    int tid = threadIdx.x;
    int lane = tid & 31, wid = tid >> 5;
    int warp_m = wid & 3, warp_n = wid >> 2;
    int rowbase = blockIdx.y * 128;
    int colbase = blockIdx.x * 128;

    const float* srcs[4] = {g_An, g_At, xn, xt};

    int arow_l = tid >> 3;
    int acol4 = tid & 7;
    int bn = tid >> 1;
    int bko = (tid & 1) * 32;

    uint32_t aoff = (uint32_t)((warp_m * 32 + (lane & 15)) * 80 + ((lane >> 4) * 16));
    uint32_t boff = (uint32_t)((warp_n * 64 + (lane & 7) + ((lane >> 4) << 3)) * 80 +
                               (((lane >> 3) & 1) * 16));

    float acc[2][8][4] = {};
    float4 pf[4];

    auto ldgA = [&](int s) {
        const float* src = srcs[s >> 2];
        int kb = (s & 3) * 32 + acol4 * 4;
        #pragma unroll
        for (int p = 0; p < 4; p++) {
            int gr = rowbase + arow_l + p * 32;
            if (gr >= M) gr = M - 1;
            pf[p] = __ldg(reinterpret_cast<const float4*>(src + (size_t)gr * INF + kb));
        }
    };
    auto stsA = [&](int par) {
        char* st = smem + par * G1_STAGE;
        #pragma unroll
        for (int p = 0; p < 4; p++) {
            int row = arow_l + p * 32;
            float4 v = pf[p];
            uint2 hi, lo;
            hi.x = pack2h(v.x, v.y);
            hi.y = pack2h(v.z, v.w);
            lo.x = pack2h(v.x - toh(v.x), v.y - toh(v.y));
            lo.y = pack2h(v.z - toh(v.z), v.w - toh(v.w));
            *reinterpret_cast<uint2*>(st + G1_AHI + row * 80 + acol4 * 8) = hi;
            *reinterpret_cast<uint2*>(st + G1_ALO + row * 80 + acol4 * 8) = lo;
        }
    };
    auto cpB = [&](int s, int par) {
        size_t srow = (size_t)(colbase + bn) * 1024 + (size_t)s * 64 + bko;
        const char* sh = reinterpret_cast<const char*>(g_Bh) + srow;
        uint32_t dh = smem_u + par * G1_STAGE + G1_BH + bn * 80 + bko;
        CP_ASYNC16(dh, sh);
        CP_ASYNC16(dh + 16, sh + 16);
        CP_COMMIT();
    };

    ldgA(0);
    cpB(0, 0);

    for (int s = 0; s < 16; s++) {
        int par = s & 1;
        stsA(par);
        if (s < 15) {
            ldgA(s + 1);
            cpB(s + 1, 1 - par);
            CP_WAIT(1);
        } else {
            CP_WAIT(0);
        }
        __syncthreads();

        uint32_t sb = smem_u + par * G1_STAGE;
        #pragma unroll
        for (int k16 = 0; k16 < 2; k16++) {
            uint32_t ah[8], al[8];
            LDSM4(ah,     sb + G1_AHI + aoff + k16 * 32);
            LDSM4(ah + 4, sb + G1_AHI + aoff + 16 * 80 + k16 * 32);
            LDSM4(al,     sb + G1_ALO + aoff + k16 * 32);
            LDSM4(al + 4, sb + G1_ALO + aoff + 16 * 80 + k16 * 32);
            uint32_t bh[16];
            #pragma unroll
            for (int nt2 = 0; nt2 < 4; nt2++)
                LDSM4(bh + nt2 * 4, sb + G1_BH + boff + nt2 * 1280 + k16 * 32);
            #pragma unroll
            for (int mt = 0; mt < 2; mt++) {
                #pragma unroll
                for (int nt = 0; nt < 8; nt++) {
                    MMA16816H(acc[mt][nt], ah + mt * 4, bh + nt * 2);
                    MMA16816H(acc[mt][nt], al + mt * 4, bh + nt * 2);
                }
            }
        }
        __syncthreads();
    }

    int gid = lane >> 2, tig = lane & 3;
    #pragma unroll
    for (int nt = 0; nt < 8; nt++) {
        int col = colbase + warp_n * 64 + nt * 8 + tig * 2;
        float bb0 = g_bB[col], bb1 = g_bB[col + 1];
        float ba0 = g_bA[col], ba1 = g_bA[col + 1];
        #pragma unroll
        for (int mt = 0; mt < 2; mt++) {
            #pragma unroll
            for (int hh = 0; hh < 2; hh++) {
                int row = rowbase + warp_m * 32 + mt * 16 + gid + hh * 8;
                if (row < M) {
                    bool c = g_cnt0[row] > 0;
                    float2 r;
                    r.x = fmaxf(acc[mt][nt][hh * 2 + 0] + bb0 + (c ? ba0 : 0.f), 0.f);
                    r.y = fmaxf(acc[mt][nt][hh * 2 + 1] + bb1 + (c ? ba1 : 0.f), 0.f);
                    *reinterpret_cast<float2*>(&g_X1[(size_t)row * HIDF + col]) = r;
                }
            }
        }
    }
}

// ======================= layer-2 HMMA GEMM + fused log_softmax =======================
__global__ __launch_bounds__(256, 1) void gemm2_mma_kernel(const float* __restrict__ b2,
                                                           float* __restrict__ out, int M) {
    __shared__ __align__(16) char smem[2 * 20480];
    const uint32_t smem_u = smem_to_u32(smem);
    int tid = threadIdx.x;
    int lane = tid & 31, wid = tid >> 5;
    int rowbase = blockIdx.x * 128;

    int arow_l = tid >> 3;
    int acol4 = tid & 7;
    uint32_t aoff = (uint32_t)((wid * 16 + (lane & 15)) * 80 + ((lane >> 4) * 16));

    float acc[8][4] = {};
    float4 pf[4];

    auto ldgA = [&](int s) {
        const float* src = (s < 8) ? g_Ag1 : g_X1;
        int kb = (s & 7) * 32 + acol4 * 4;
        #pragma unroll
        for (int p = 0; p < 4; p++) {
            int gr = rowbase + arow_l + p * 32;
            if (gr >= M) gr = M - 1;
            pf[p] = __ldg(reinterpret_cast<const float4*>(src + (size_t)gr * HIDF + kb));
        }
    };
    auto stsA = [&](int par) {
        char* st = smem + par * 20480;
        #pragma unroll
        for (int p = 0; p < 4; p++) {
            int row = arow_l + p * 32;
            float4 v = pf[p];
            uint2 hi, lo;
            hi.x = pack2h(v.x, v.y);
            hi.y = pack2h(v.z, v.w);
            lo.x = pack2h(v.x - toh(v.x), v.y - toh(v.y));
            lo.y = pack2h(v.z - toh(v.z), v.w - toh(v.w));
            *reinterpret_cast<uint2*>(st + row * 80 + acol4 * 8) = hi;
            *reinterpret_cast<uint2*>(st + 10240 + row * 80 + acol4 * 8) = lo;
        }
    };

    ldgA(0);
    for (int s = 0; s < 16; s++) {
        int par = s & 1;
        stsA(par);
        if (s < 15) ldgA(s + 1);
        __syncthreads();
        uint32_t sb = smem_u + par * 20480;
        #pragma unroll
        for (int kk = 0; kk < 2; kk++) {
            int k16 = s * 2 + kk;
            uint32_t ah[4], al[4];
            LDSM4(ah, sb + aoff + kk * 32);
            LDSM4(al, sb + 10240 + aoff + kk * 32);
            #pragma unroll
            for (int nt = 0; nt < 8; nt++) {
                uint2 bh = __ldg(reinterpret_cast<const uint2*>(
                    g_W2f + ((size_t)(k16 * 8 + nt) * 32 + lane) * 2));
                MMA16816H(acc[nt], ah, reinterpret_cast<uint32_t*>(&bh));
                MMA16816H(acc[nt], al, reinterpret_cast<uint32_t*>(&bh));
            }
        }
        __syncthreads();
    }

    int gid = lane >> 2, tig = lane & 3;
    #pragma unroll
    for (int hh = 0; hh < 2; hh++) {
        int row = rowbase + wid * 16 + gid + hh * 8;
        float v[16];
        float m = -1e30f;
        #pragma unroll
        for (int nt = 0; nt < 8; nt++) {
            int col = nt * 8 + tig * 2;
            v[nt * 2 + 0] = acc[nt][hh * 2 + 0] + b2[col];
            v[nt * 2 + 1] = acc[nt][hh * 2 + 1] + b2[col + 1];
            m = fmaxf(m, fmaxf(v[nt * 2], v[nt * 2 + 1]));
        }
        m = fmaxf(m, __shfl_xor_sync(0xffffffffu, m, 1));
        m = fmaxf(m, __shfl_xor_sync(0xffffffffu, m, 2));
        float se = 0.f;
        #pragma unroll
        for (int i = 0; i < 16; i++) se += expf(v[i] - m);
        se += __shfl_xor_sync(0xffffffffu, se, 1);
        se += __shfl_xor_sync(0xffffffffu, se, 2);
        float lse = m + logf(se);
        if (row < M) {
            #pragma unroll
            for (int nt = 0; nt < 8; nt++) {
                float2 r;
                r.x = v[nt * 2 + 0] - lse;
                r.y = v[nt * 2 + 1] - lse;
                *reinterpret_cast<float2*>(&out[(size_t)row * OUTF + nt * 8 + tig * 2]) = r;
            }
        }
    }
}

// ======================= launch =======================
extern "C" void kernel_launch(void* const* d_in, const int* in_sizes, int n_in,
                              void* d_out, int out_size) {
    const float* x_tar   = (const float*)d_in[0];
    const float* x_neigh = (const float*)d_in[1];
    const int* esrc0 = (const int*)d_in[2];
    const int* edst0 = (const int*)d_in[3];
    const int* esrc1 = (const int*)d_in[4];
    const int* edst1 = (const int*)d_in[5];
    const float* Wl0 = (const float*)d_in[8];
    const float* Wr0 = (const float*)d_in[9];
    const float* b0  = (const float*)d_in[10];
    const float* Wl1 = (const float*)d_in[11];
    const float* Wr1 = (const float*)d_in[12];
    const float* b1  = (const float*)d_in[13];
    const float* Wl2 = (const float*)d_in[14];
    const float* Wr2 = (const float*)d_in[15];
    const float* b2  = (const float*)d_in[16];
    int E0 = in_sizes[2];
    int E1 = in_sizes[4];
    int M1 = N1C;
    int M2 = out_size / OUTF;
    float* out = (float*)d_out;

    cudaFuncSetAttribute(gemm1_mma_kernel,
                         cudaFuncAttributeMaxDynamicSharedMemorySize, GEMM1_SMEM);

    zero_prep_kernel<<<ZB + WCB + W2B + 1, 256>>>(Wl0, Wr0, b0, Wl1, Wr1, b1, Wl2, Wr2);

    int EALL = E0 + E1;
    countAll_kernel<<<(EALL + 255) / 256, 256>>>(edst0, edst1, E0, E1);
    scanLB_kernel<<<NB0 + NB1, 256>>>();
    scatterAll_kernel<<<(EALL + 255) / 256, 256>>>(esrc0, edst0, esrc1, edst1, E0, E1);
    agg0_kernel<<<(N1C + 3) / 4, 256>>>(x_neigh, x_tar);

    dim3 g1(2, (M1 + 127) / 128);
    gemm1_mma_kernel<<<g1, 256, GEMM1_SMEM>>>(x_neigh, x_tar, M1);

    agg1_kernel<<<(N2C + 3) / 4, 256>>>();
    gemm2_mma_kernel<<<(M2 + 127) / 128, 256>>>(b2, out, M2);
}

// round 7
// speedup vs baseline: 1.2744x; 1.2744x over previous
#include <cuda_runtime.h>
#include <cuda_bf16.h>
#include <cuda_fp16.h>
#include <cstdint>

#define INF   128
#define HIDF  256
#define OUTF  64
#define N1C   100000
#define N2C   25000
#define E0C   1600000
#define E1C   400000

// ======================= PTX helpers =======================
__device__ __forceinline__ uint32_t smem_to_u32(const void* smem_ptr) {
    uint32_t addr;
    asm("{ .reg .u64 tmp; cvta.to.shared.u64 tmp, %1; cvt.u32.u64 %0, tmp; }"
        : "=r"(addr) : "l"(smem_ptr));
    return addr;
}
#define CP_ASYNC16(dst, src) \
    asm volatile("cp.async.cg.shared.global [%0], [%1], 16;" :: "r"(dst), "l"(src))
#define CP_COMMIT() asm volatile("cp.async.commit_group;" ::: "memory")
#define CP_WAIT(n)  asm volatile("cp.async.wait_group %0;" :: "n"(n) : "memory")
#define LDSM4(r, addr) \
    asm volatile("ldmatrix.sync.aligned.m8n8.x4.shared.b16 {%0,%1,%2,%3}, [%4];" \
        : "=r"((r)[0]), "=r"((r)[1]), "=r"((r)[2]), "=r"((r)[3]) : "r"(addr))
#define MMA16816H(d, a, b) \
    asm volatile("mma.sync.aligned.m16n8k16.row.col.f32.f16.f16.f32 " \
        "{%0,%1,%2,%3}, {%4,%5,%6,%7}, {%8,%9}, {%0,%1,%2,%3};" \
        : "+f"((d)[0]), "+f"((d)[1]), "+f"((d)[2]), "+f"((d)[3]) \
        : "r"((a)[0]), "r"((a)[1]), "r"((a)[2]), "r"((a)[3]), \
          "r"((b)[0]), "r"((b)[1]))

__device__ __forceinline__ uint32_t pack2h(float a, float b) {
    __half2 p = __floats2half2_rn(a, b);
    return *reinterpret_cast<uint32_t*>(&p);
}
__device__ __forceinline__ float toh(float x) {
    return __half2float(__float2half_rn(x));
}

// ======================= device scratch =======================
__device__ __align__(16) float g_An[(size_t)N1C * INF];
__device__ __align__(16) float g_At[(size_t)N1C * INF];
__device__ __align__(16) float g_X1[(size_t)N1C * HIDF];
__device__ __align__(16) float g_Ag1[(size_t)N2C * HIDF];
__device__ int g_cnt0[N1C];
__device__ int g_off0[N1C + 1];
__device__ int g_cur0[N1C];
__device__ int g_es0[E0C];
__device__ int g_cnt1[N2C];
__device__ int g_off1[N2C + 1];
__device__ int g_cur1[N2C];
__device__ int g_es1[E1C];
__device__ int g_part0[256];
__device__ int g_part1[64];
__device__ __align__(128) __half g_Bh[256 * 512];           // [N=256][K=512] combined W fp16
__device__ __align__(16) uint32_t g_W2f[64 * 512 / 2];      // W2 fp16, mma fragment order
__device__ float g_bA[HIDF];
__device__ float g_bB[HIDF];

// ======================= fused zero + weight prep =======================
#define ZB  489
#define WCB 512
#define W2B 128
__global__ void zero_prep_kernel(
    const float* __restrict__ Wl0, const float* __restrict__ Wr0,
    const float* __restrict__ b0,
    const float* __restrict__ Wl1, const float* __restrict__ Wr1,
    const float* __restrict__ b1,
    const float* __restrict__ Wl2, const float* __restrict__ Wr2) {
    int b = blockIdx.x, t = threadIdx.x;
    if (b < ZB) {
        int i = b * 256 + t;
        if (i < N1C) g_cnt0[i] = 0;
        else if (i < N1C + N2C) g_cnt1[i - N1C] = 0;
    } else if (b < ZB + WCB) {
        int idx = (b - ZB) * 256 + t;
        int i = idx >> 8;                  // K 0..511
        int j = idx & 255;                 // N 0..255
        int blk = i >> 7;
        int il = i & 127;
        const float* M1 = (blk == 0 || blk == 2) ? Wl0 : Wr0;
        const float* M2 = (blk < 2) ? Wl1 : Wr1;
        float s = 0.f;
        #pragma unroll 8
        for (int k = 0; k < 256; k++) s = fmaf(M1[il * 256 + k], M2[k * 256 + j], s);
        g_Bh[j * 512 + i] = __float2half_rn(s);
    } else if (b < ZB + WCB + W2B) {
        int e = (b - ZB - WCB) * 256 + t;
        int n = e & 63, k = e >> 6;
        float s = (k < 256) ? Wl2[k * 64 + n] : Wr2[(k - 256) * 64 + n];
        int k16 = k >> 4, nt = n >> 3, gid = n & 7;
        int kk = k & 15, reg = kk >> 3, tig = (kk & 7) >> 1, half = kk & 1;
        int u = ((k16 * 8 + nt) * 32 + gid * 4 + tig) * 2 + reg;
        reinterpret_cast<__half*>(g_W2f)[u * 2 + half] = __float2half_rn(s);
    } else {
        int j = t;
        float sa = 0.f, sb = 0.f;
        for (int k = 0; k < 256; k++) {
            sa = fmaf(b0[k], Wl1[k * 256 + j], sa);
            sb = fmaf(b0[k], Wr1[k * 256 + j], sb);
        }
        g_bA[j] = sa;
        g_bB[j] = sb + b1[j];
    }
}

// ======================= merged bookkeeping =======================
__global__ void countAll_kernel(const int* __restrict__ d0, const int* __restrict__ d1,
                                int e0, int e1) {
    int i = blockIdx.x * blockDim.x + threadIdx.x;
    if (i < e0) atomicAdd(&g_cnt0[d0[i]], 1);
    else if (i - e0 < e1) atomicAdd(&g_cnt1[d1[i - e0]], 1);
}
__global__ void scatterAll_kernel(const int* __restrict__ s0, const int* __restrict__ d0,
                                  const int* __restrict__ s1, const int* __restrict__ d1,
                                  int e0, int e1) {
    int i = blockIdx.x * blockDim.x + threadIdx.x;
    if (i < e0) {
        int p = atomicAdd(&g_cur0[d0[i]], 1);
        g_es0[p] = s0[i];
    } else if (i - e0 < e1) {
        int j = i - e0;
        int p = atomicAdd(&g_cur1[d1[j]], 1);
        g_es1[p] = s1[j];
    }
}

#define NB0 ((N1C + 511) / 512)
#define NB1 ((N2C + 511) / 512)

__device__ __forceinline__ void scan_part_impl(const int* __restrict__ cnt,
                                               int* __restrict__ part, int n, int bb) {
    __shared__ int ws[8];
    int base = bb * 512;
    int t = threadIdx.x;
    int i0 = base + t * 2;
    int s = 0;
    if (i0 < n) s += cnt[i0];
    if (i0 + 1 < n) s += cnt[i0 + 1];
    #pragma unroll
    for (int o = 16; o > 0; o >>= 1) s += __shfl_down_sync(0xffffffffu, s, o);
    if ((t & 31) == 0) ws[t >> 5] = s;
    __syncthreads();
    if (t == 0) {
        int tot = 0;
        #pragma unroll
        for (int i = 0; i < 8; i++) tot += ws[i];
        part[bb] = tot;
    }
}
__device__ __forceinline__ void scan_top_impl(int* __restrict__ part, int nb) {
    __shared__ int ws[8];
    int t = threadIdx.x;
    int v = (t < nb) ? part[t] : 0;
    int lane = t & 31, w = t >> 5;
    int incl = v;
    #pragma unroll
    for (int o = 1; o < 32; o <<= 1) {
        int x = __shfl_up_sync(0xffffffffu, incl, o);
        if (lane >= o) incl += x;
    }
    if (lane == 31) ws[w] = incl;
    __syncthreads();
    if (t == 0) {
        int run = 0;
        #pragma unroll
        for (int i = 0; i < 8; i++) { int tm = ws[i]; ws[i] = run; run += tm; }
    }
    __syncthreads();
    if (t < nb) part[t] = incl - v + ws[w];
    __syncthreads();
}
__device__ __forceinline__ void scan_final_impl(const int* __restrict__ cnt,
                                                const int* __restrict__ part,
                                                int* __restrict__ off,
                                                int* __restrict__ cur, int n, int bb) {
    __shared__ int ws[8];
    int base = bb * 512;
    int t = threadIdx.x;
    int i0 = base + t * 2;
    int c0 = (i0 < n) ? cnt[i0] : 0;
    int c1 = (i0 + 1 < n) ? cnt[i0 + 1] : 0;
    int s = c0 + c1;
    int lane = t & 31, w = t >> 5;
    int incl = s;
    #pragma unroll
    for (int o = 1; o < 32; o <<= 1) {
        int x = __shfl_up_sync(0xffffffffu, incl, o);
        if (lane >= o) incl += x;
    }
    if (lane == 31) ws[w] = incl;
    __syncthreads();
    if (t == 0) {
        int run = 0;
        #pragma unroll
        for (int i = 0; i < 8; i++) { int tm = ws[i]; ws[i] = run; run += tm; }
    }
    __syncthreads();
    int excl = incl - s + ws[w] + part[bb];
    if (i0 < n) { off[i0] = excl; cur[i0] = excl; }
    if (i0 + 1 < n) { off[i0 + 1] = excl + c0; cur[i0 + 1] = excl + c0; }
    if (i0 == n - 1) off[n] = excl + c0;
    else if (i0 + 1 == n - 1) off[n] = excl + c0 + c1;
}
__global__ void scanPart_all() {
    int b = blockIdx.x;
    if (b < NB0) scan_part_impl(g_cnt0, g_part0, N1C, b);
    else scan_part_impl(g_cnt1, g_part1, N2C, b - NB0);
}
__global__ void scanTop_all() {
    scan_top_impl(g_part0, NB0);
    scan_top_impl(g_part1, NB1);
}
__global__ void scanFinal_all() {
    int b = blockIdx.x;
    if (b < NB0) scan_final_impl(g_cnt0, g_part0, g_off0, g_cur0, N1C, b);
    else scan_final_impl(g_cnt1, g_part1, g_off1, g_cur1, N2C, b - NB0);
}

// ======================= aggregation =======================
__global__ __launch_bounds__(256) void agg0_kernel(const float* __restrict__ xn,
                                                   const float* __restrict__ xt) {
    int w = threadIdx.x >> 5, lane = threadIdx.x & 31;
    int d = blockIdx.x * 4 + (w >> 1);
    if (d >= N1C) return;
    const float* src = (w & 1) ? xt : xn;
    float* dstp = (w & 1) ? g_At : g_An;
    int b = g_off0[d], e = g_off0[d + 1];
    float4 acc = make_float4(0.f, 0.f, 0.f, 0.f);
    int i = b;
    for (; i + 3 < e; i += 4) {
        int s0 = g_es0[i], s1 = g_es0[i + 1], s2 = g_es0[i + 2], s3 = g_es0[i + 3];
        float4 v0 = __ldg(reinterpret_cast<const float4*>(src + (size_t)s0 * INF) + lane);
        float4 v1 = __ldg(reinterpret_cast<const float4*>(src + (size_t)s1 * INF) + lane);
        float4 v2 = __ldg(reinterpret_cast<const float4*>(src + (size_t)s2 * INF) + lane);
        float4 v3 = __ldg(reinterpret_cast<const float4*>(src + (size_t)s3 * INF) + lane);
        acc.x += (v0.x + v1.x) + (v2.x + v3.x);
        acc.y += (v0.y + v1.y) + (v2.y + v3.y);
        acc.z += (v0.z + v1.z) + (v2.z + v3.z);
        acc.w += (v0.w + v1.w) + (v2.w + v3.w);
    }
    for (; i < e; i++) {
        int s0 = g_es0[i];
        float4 v0 = __ldg(reinterpret_cast<const float4*>(src + (size_t)s0 * INF) + lane);
        acc.x += v0.x; acc.y += v0.y; acc.z += v0.z; acc.w += v0.w;
    }
    float inv = (e > b) ? 1.f / (float)(e - b) : 0.f;
    acc.x *= inv; acc.y *= inv; acc.z *= inv; acc.w *= inv;
    reinterpret_cast<float4*>(dstp + (size_t)d * INF)[lane] = acc;
}

__global__ __launch_bounds__(256) void agg1_kernel() {
    int w = threadIdx.x >> 5, lane = threadIdx.x & 31;
    int d = blockIdx.x * 4 + (w >> 1);
    if (d >= N2C) return;
    int colb = (w & 1) * 128;
    int b = g_off1[d], e = g_off1[d + 1];
    float4 acc = make_float4(0.f, 0.f, 0.f, 0.f);
    int i = b;
    for (; i + 1 < e; i += 2) {
        int s0 = g_es1[i], s1 = g_es1[i + 1];
        float4 v0 = __ldg(reinterpret_cast<const float4*>(g_X1 + (size_t)s0 * HIDF + colb) + lane);
        float4 v1 = __ldg(reinterpret_cast<const float4*>(g_X1 + (size_t)s1 * HIDF + colb) + lane);
        acc.x += v0.x + v1.x; acc.y += v0.y + v1.y;
        acc.z += v0.z + v1.z; acc.w += v0.w + v1.w;
    }
    if (i < e) {
        int s0 = g_es1[i];
        float4 v0 = __ldg(reinterpret_cast<const float4*>(g_X1 + (size_t)s0 * HIDF + colb) + lane);
        acc.x += v0.x; acc.y += v0.y; acc.z += v0.z; acc.w += v0.w;
    }
    float inv = (e > b) ? 1.f / (float)(e - b) : 0.f;
    acc.x *= inv; acc.y *= inv; acc.z *= inv; acc.w *= inv;
    reinterpret_cast<float4*>(g_Ag1 + (size_t)d * HIDF + colb)[lane] = acc;
}

// ======================= HMMA fused layer-0+1 GEMM (fp16 2-term split) ================
// X1 = relu([A_n|A_t|xn_t|xt_t](K=512) @ Bh(512x256,fp16) + bias)
// D = Ahi@B + Alo@B; A split fp16 hi/lo (exact to 2^-24), B single fp16.
// CTA 128x128, 8 warps (warp tile 32x64), BK=32, double buffered; rows padded to 80B.
#define G1_AHI     0
#define G1_ALO     10240
#define G1_BH      20480
#define G1_STAGE   30720
#define GEMM1_SMEM (2 * G1_STAGE)

__global__ __launch_bounds__(256, 1) void gemm1_mma_kernel(const float* __restrict__ xn,
                                                           const float* __restrict__ xt,
                                                           int M) {
    extern __shared__ char smem[];
    const uint32_t smem_u = smem_to_u32(smem);
    int tid = threadIdx.x;
    int lane = tid & 31, wid = tid >> 5;
    int warp_m = wid & 3, warp_n = wid >> 2;
    int rowbase = blockIdx.y * 128;
    int colbase = blockIdx.x * 128;

    const float* srcs[4] = {g_An, g_At, xn, xt};

    int arow_l = tid >> 3;
    int acol4 = tid & 7;
    int bn = tid >> 1;
    int bko = (tid & 1) * 32;

    uint32_t aoff = (uint32_t)((warp_m * 32 + (lane & 15)) * 80 + ((lane >> 4) * 16));
    uint32_t boff = (uint32_t)((warp_n * 64 + (lane & 7) + ((lane >> 4) << 3)) * 80 +
                               (((lane >> 3) & 1) * 16));

    float acc[2][8][4] = {};
    float4 pf[4];

    auto ldgA = [&](int s) {
        const float* src = srcs[s >> 2];
        int kb = (s & 3) * 32 + acol4 * 4;
        #pragma unroll
        for (int p = 0; p < 4; p++) {
            int gr = rowbase + arow_l + p * 32;
            if (gr >= M) gr = M - 1;
            pf[p] = __ldg(reinterpret_cast<const float4*>(src + (size_t)gr * INF + kb));
        }
    };
    auto stsA = [&](int par) {
        char* st = smem + par * G1_STAGE;
        #pragma unroll
        for (int p = 0; p < 4; p++) {
            int row = arow_l + p * 32;
            float4 v = pf[p];
            uint2 hi, lo;
            hi.x = pack2h(v.x, v.y);
            hi.y = pack2h(v.z, v.w);
            lo.x = pack2h(v.x - toh(v.x), v.y - toh(v.y));
            lo.y = pack2h(v.z - toh(v.z), v.w - toh(v.w));
            *reinterpret_cast<uint2*>(st + G1_AHI + row * 80 + acol4 * 8) = hi;
            *reinterpret_cast<uint2*>(st + G1_ALO + row * 80 + acol4 * 8) = lo;
        }
    };
    auto cpB = [&](int s, int par) {
        size_t srow = (size_t)(colbase + bn) * 1024 + (size_t)s * 64 + bko;
        const char* sh = reinterpret_cast<const char*>(g_Bh) + srow;
        uint32_t dh = smem_u + par * G1_STAGE + G1_BH + bn * 80 + bko;
        CP_ASYNC16(dh, sh);
        CP_ASYNC16(dh + 16, sh + 16);
        CP_COMMIT();
    };

    ldgA(0);
    cpB(0, 0);

    for (int s = 0; s < 16; s++) {
        int par = s & 1;
        stsA(par);
        if (s < 15) {
            ldgA(s + 1);
            cpB(s + 1, 1 - par);
            CP_WAIT(1);
        } else {
            CP_WAIT(0);
        }
        __syncthreads();

        uint32_t sb = smem_u + par * G1_STAGE;
        #pragma unroll
        for (int k16 = 0; k16 < 2; k16++) {
            uint32_t ah[8], al[8];
            LDSM4(ah,     sb + G1_AHI + aoff + k16 * 32);
            LDSM4(ah + 4, sb + G1_AHI + aoff + 16 * 80 + k16 * 32);
            LDSM4(al,     sb + G1_ALO + aoff + k16 * 32);
            LDSM4(al + 4, sb + G1_ALO + aoff + 16 * 80 + k16 * 32);
            uint32_t bh[16];
            #pragma unroll
            for (int nt2 = 0; nt2 < 4; nt2++)
                LDSM4(bh + nt2 * 4, sb + G1_BH + boff + nt2 * 1280 + k16 * 32);
            #pragma unroll
            for (int mt = 0; mt < 2; mt++) {
                #pragma unroll
                for (int nt = 0; nt < 8; nt++) {
                    MMA16816H(acc[mt][nt], ah + mt * 4, bh + nt * 2);
                    MMA16816H(acc[mt][nt], al + mt * 4, bh + nt * 2);
                }
            }
        }
        __syncthreads();
    }

    int gid = lane >> 2, tig = lane & 3;
    #pragma unroll
    for (int nt = 0; nt < 8; nt++) {
        int col = colbase + warp_n * 64 + nt * 8 + tig * 2;
        float bb0 = g_bB[col], bb1 = g_bB[col + 1];
        float ba0 = g_bA[col], ba1 = g_bA[col + 1];
        #pragma unroll
        for (int mt = 0; mt < 2; mt++) {
            #pragma unroll
            for (int hh = 0; hh < 2; hh++) {
                int row = rowbase + warp_m * 32 + mt * 16 + gid + hh * 8;
                if (row < M) {
                    bool c = g_cnt0[row] > 0;
                    float2 r;
                    r.x = fmaxf(acc[mt][nt][hh * 2 + 0] + bb0 + (c ? ba0 : 0.f), 0.f);
                    r.y = fmaxf(acc[mt][nt][hh * 2 + 1] + bb1 + (c ? ba1 : 0.f), 0.f);
                    *reinterpret_cast<float2*>(&g_X1[(size_t)row * HIDF + col]) = r;
                }
            }
        }
    }
}

// ======================= layer-2 HMMA GEMM + fused log_softmax =======================
__global__ __launch_bounds__(256, 1) void gemm2_mma_kernel(const float* __restrict__ b2,
                                                           float* __restrict__ out, int M) {
    __shared__ __align__(16) char smem[2 * 20480];
    const uint32_t smem_u = smem_to_u32(smem);
    int tid = threadIdx.x;
    int lane = tid & 31, wid = tid >> 5;
    int rowbase = blockIdx.x * 128;

    int arow_l = tid >> 3;
    int acol4 = tid & 7;
    uint32_t aoff = (uint32_t)((wid * 16 + (lane & 15)) * 80 + ((lane >> 4) * 16));

    float acc[8][4] = {};
    float4 pf[4];

    auto ldgA = [&](int s) {
        const float* src = (s < 8) ? g_Ag1 : g_X1;
        int kb = (s & 7) * 32 + acol4 * 4;
        #pragma unroll
        for (int p = 0; p < 4; p++) {
            int gr = rowbase + arow_l + p * 32;
            if (gr >= M) gr = M - 1;
            pf[p] = __ldg(reinterpret_cast<const float4*>(src + (size_t)gr * HIDF + kb));
        }
    };
    auto stsA = [&](int par) {
        char* st = smem + par * 20480;
        #pragma unroll
        for (int p = 0; p < 4; p++) {
            int row = arow_l + p * 32;
            float4 v = pf[p];
            uint2 hi, lo;
            hi.x = pack2h(v.x, v.y);
            hi.y = pack2h(v.z, v.w);
            lo.x = pack2h(v.x - toh(v.x), v.y - toh(v.y));
            lo.y = pack2h(v.z - toh(v.z), v.w - toh(v.w));
            *reinterpret_cast<uint2*>(st + row * 80 + acol4 * 8) = hi;
            *reinterpret_cast<uint2*>(st + 10240 + row * 80 + acol4 * 8) = lo;
        }
    };

    ldgA(0);
    for (int s = 0; s < 16; s++) {
        int par = s & 1;
        stsA(par);
        if (s < 15) ldgA(s + 1);
        __syncthreads();
        uint32_t sb = smem_u + par * 20480;
        #pragma unroll
        for (int kk = 0; kk < 2; kk++) {
            int k16 = s * 2 + kk;
            uint32_t ah[4], al[4];
            LDSM4(ah, sb + aoff + kk * 32);
            LDSM4(al, sb + 10240 + aoff + kk * 32);
            #pragma unroll
            for (int nt = 0; nt < 8; nt++) {
                uint2 bh = __ldg(reinterpret_cast<const uint2*>(
                    g_W2f + ((size_t)(k16 * 8 + nt) * 32 + lane) * 2));
                MMA16816H(acc[nt], ah, reinterpret_cast<uint32_t*>(&bh));
                MMA16816H(acc[nt], al, reinterpret_cast<uint32_t*>(&bh));
            }
        }
        __syncthreads();
    }

    int gid = lane >> 2, tig = lane & 3;
    #pragma unroll
    for (int hh = 0; hh < 2; hh++) {
        int row = rowbase + wid * 16 + gid + hh * 8;
        float v[16];
        float m = -1e30f;
        #pragma unroll
        for (int nt = 0; nt < 8; nt++) {
            int col = nt * 8 + tig * 2;
            v[nt * 2 + 0] = acc[nt][hh * 2 + 0] + b2[col];
            v[nt * 2 + 1] = acc[nt][hh * 2 + 1] + b2[col + 1];
            m = fmaxf(m, fmaxf(v[nt * 2], v[nt * 2 + 1]));
        }
        m = fmaxf(m, __shfl_xor_sync(0xffffffffu, m, 1));
        m = fmaxf(m, __shfl_xor_sync(0xffffffffu, m, 2));
        float se = 0.f;
        #pragma unroll
        for (int i = 0; i < 16; i++) se += expf(v[i] - m);
        se += __shfl_xor_sync(0xffffffffu, se, 1);
        se += __shfl_xor_sync(0xffffffffu, se, 2);
        float lse = m + logf(se);
        if (row < M) {
            #pragma unroll
            for (int nt = 0; nt < 8; nt++) {
                float2 r;
                r.x = v[nt * 2 + 0] - lse;
                r.y = v[nt * 2 + 1] - lse;
                *reinterpret_cast<float2*>(&out[(size_t)row * OUTF + nt * 8 + tig * 2]) = r;
            }
        }
    }
}

// ======================= launch =======================
extern "C" void kernel_launch(void* const* d_in, const int* in_sizes, int n_in,
                              void* d_out, int out_size) {
    const float* x_tar   = (const float*)d_in[0];
    const float* x_neigh = (const float*)d_in[1];
    const int* esrc0 = (const int*)d_in[2];
    const int* edst0 = (const int*)d_in[3];
    const int* esrc1 = (const int*)d_in[4];
    const int* edst1 = (const int*)d_in[5];
    const float* Wl0 = (const float*)d_in[8];
    const float* Wr0 = (const float*)d_in[9];
    const float* b0  = (const float*)d_in[10];
    const float* Wl1 = (const float*)d_in[11];
    const float* Wr1 = (const float*)d_in[12];
    const float* b1  = (const float*)d_in[13];
    const float* Wl2 = (const float*)d_in[14];
    const float* Wr2 = (const float*)d_in[15];
    const float* b2  = (const float*)d_in[16];
    int E0 = in_sizes[2];
    int E1 = in_sizes[4];
    int M1 = N1C;
    int M2 = out_size / OUTF;
    float* out = (float*)d_out;

    cudaFuncSetAttribute(gemm1_mma_kernel,
                         cudaFuncAttributeMaxDynamicSharedMemorySize, GEMM1_SMEM);

    zero_prep_kernel<<<ZB + WCB + W2B + 1, 256>>>(Wl0, Wr0, b0, Wl1, Wr1, b1, Wl2, Wr2);

    int EALL = E0 + E1;
    countAll_kernel<<<(EALL + 255) / 256, 256>>>(edst0, edst1, E0, E1);
    scanPart_all<<<NB0 + NB1, 256>>>();
    scanTop_all<<<1, 256>>>();
    scanFinal_all<<<NB0 + NB1, 256>>>();
    scatterAll_kernel<<<(EALL + 255) / 256, 256>>>(esrc0, edst0, esrc1, edst1, E0, E1);
    agg0_kernel<<<(N1C + 3) / 4, 256>>>(x_neigh, x_tar);

    dim3 g1(2, (M1 + 127) / 128);
    gemm1_mma_kernel<<<g1, 256, GEMM1_SMEM>>>(x_neigh, x_tar, M1);

    agg1_kernel<<<(N2C + 3) / 4, 256>>>();
    gemm2_mma_kernel<<<(M2 + 127) / 128, 256>>>(b2, out, M2);
}

// round 8
// speedup vs baseline: 1.7541x; 1.3763x over previous
#include <cuda_runtime.h>
#include <cuda_fp16.h>
#include <cstdint>

#define INF   128
#define HIDF  256
#define OUTF  64
#define N0C   400000
#define N1C   100000
#define N2C   25000
#define E0C   1600000
#define E1C   400000

// ======================= PTX helpers =======================
__device__ __forceinline__ uint32_t smem_to_u32(const void* smem_ptr) {
    uint32_t addr;
    asm("{ .reg .u64 tmp; cvta.to.shared.u64 tmp, %1; cvt.u32.u64 %0, tmp; }"
        : "=r"(addr) : "l"(smem_ptr));
    return addr;
}
#define CP_ASYNC16(dst, src) \
    asm volatile("cp.async.cg.shared.global [%0], [%1], 16;" :: "r"(dst), "l"(src))
#define CP_COMMIT() asm volatile("cp.async.commit_group;" ::: "memory")
#define CP_WAIT(n)  asm volatile("cp.async.wait_group %0;" :: "n"(n) : "memory")
#define LDSM4(r, addr) \
    asm volatile("ldmatrix.sync.aligned.m8n8.x4.shared.b16 {%0,%1,%2,%3}, [%4];" \
        : "=r"((r)[0]), "=r"((r)[1]), "=r"((r)[2]), "=r"((r)[3]) : "r"(addr))
#define MMA16816H(d, a, b) \
    asm volatile("mma.sync.aligned.m16n8k16.row.col.f32.f16.f16.f32 " \
        "{%0,%1,%2,%3}, {%4,%5,%6,%7}, {%8,%9}, {%0,%1,%2,%3};" \
        : "+f"((d)[0]), "+f"((d)[1]), "+f"((d)[2]), "+f"((d)[3]) \
        : "r"((a)[0]), "r"((a)[1]), "r"((a)[2]), "r"((a)[3]), \
          "r"((b)[0]), "r"((b)[1]))

__device__ __forceinline__ uint32_t pack2h(float a, float b) {
    __half2 p = __floats2half2_rn(a, b);
    return *reinterpret_cast<uint32_t*>(&p);
}

// ======================= device scratch =======================
__device__ __align__(16) __half g_xc[(size_t)N0C * 256];    // [row][xn(128)|xt(128)] fp16
__device__ __align__(16) __half g_Ac[(size_t)N1C * 256];    // [row][An(128)|At(128)] fp16
__device__ __align__(16) __half g_X1h[(size_t)N1C * HIDF];  // layer-1 output fp16
__device__ __align__(16) __half g_Ag1h[(size_t)N2C * HIDF]; // level-1 aggregate fp16
__device__ int g_cnt0[N1C];
__device__ int g_off0[N1C + 1];
__device__ int g_cur0[N1C];
__device__ int g_es0[E0C];
__device__ int g_cnt1[N2C];
__device__ int g_off1[N2C + 1];
__device__ int g_cur1[N2C];
__device__ int g_es1[E1C];
__device__ int g_part0[256];
__device__ int g_part1[64];
__device__ __align__(128) __half g_Bh[256 * 512];           // [N=256][K=512] combined W fp16
__device__ __align__(16) uint32_t g_W2f[64 * 512 / 2];      // W2 fp16, mma fragment order
__device__ float g_bA[HIDF];
__device__ float g_bB[HIDF];

// ======================= fused zero + weight prep + x->fp16 convert ===================
#define ZB  489
#define WCB 512
#define W2B 128
#define CVB ((N0C * 256) / 2048)   // 50000 convert blocks (8 rows per block)
__global__ void zero_prep_kernel(
    const float* __restrict__ xn, const float* __restrict__ xt,
    const float* __restrict__ Wl0, const float* __restrict__ Wr0,
    const float* __restrict__ b0,
    const float* __restrict__ Wl1, const float* __restrict__ Wr1,
    const float* __restrict__ b1,
    const float* __restrict__ Wl2, const float* __restrict__ Wr2) {
    int b = blockIdx.x, t = threadIdx.x;
    if (b < ZB) {
        int i = b * 256 + t;
        if (i < N1C) g_cnt0[i] = 0;
        else if (i < N1C + N2C) g_cnt1[i - N1C] = 0;
    } else if (b < ZB + WCB) {
        int idx = (b - ZB) * 256 + t;
        int i = idx >> 8;                  // K 0..511
        int j = idx & 255;                 // N 0..255
        int blk = i >> 7;
        int il = i & 127;
        const float* M1 = (blk == 0 || blk == 2) ? Wl0 : Wr0;
        const float* M2 = (blk < 2) ? Wl1 : Wr1;
        float s = 0.f;
        #pragma unroll 8
        for (int k = 0; k < 256; k++) s = fmaf(M1[il * 256 + k], M2[k * 256 + j], s);
        g_Bh[j * 512 + i] = __float2half_rn(s);
    } else if (b < ZB + WCB + W2B) {
        int e = (b - ZB - WCB) * 256 + t;
        int n = e & 63, k = e >> 6;
        float s = (k < 256) ? Wl2[k * 64 + n] : Wr2[(k - 256) * 64 + n];
        int k16 = k >> 4, nt = n >> 3, gid = n & 7;
        int kk = k & 15, reg = kk >> 3, tig = (kk & 7) >> 1, half = kk & 1;
        int u = ((k16 * 8 + nt) * 32 + gid * 4 + tig) * 2 + reg;
        reinterpret_cast<__half*>(g_W2f)[u * 2 + half] = __float2half_rn(s);
    } else if (b == ZB + WCB + W2B) {
        int j = t;
        float sa = 0.f, sb = 0.f;
        for (int k = 0; k < 256; k++) {
            sa = fmaf(b0[k], Wl1[k * 256 + j], sa);
            sb = fmaf(b0[k], Wr1[k * 256 + j], sb);
        }
        g_bA[j] = sa;
        g_bB[j] = sb + b1[j];
    } else {
        // convert x -> g_xc fp16 interleaved: row = [xn(128) | xt(128)]
        int cb = b - (ZB + WCB + W2B + 1);
        int idx = cb * 2048 + t * 8;
        int row = idx >> 8;
        int pos = idx & 255;
        const float* src = (pos < 128) ? (xn + (size_t)row * 128 + pos)
                                       : (xt + (size_t)row * 128 + (pos - 128));
        float4 a = __ldg(reinterpret_cast<const float4*>(src));
        float4 c = __ldg(reinterpret_cast<const float4*>(src) + 1);
        uint4 o;
        o.x = pack2h(a.x, a.y);
        o.y = pack2h(a.z, a.w);
        o.z = pack2h(c.x, c.y);
        o.w = pack2h(c.z, c.w);
        *reinterpret_cast<uint4*>(g_xc + (size_t)row * 256 + pos) = o;
    }
}

// ======================= merged bookkeeping =======================
__global__ void countAll_kernel(const int* __restrict__ d0, const int* __restrict__ d1,
                                int e0, int e1) {
    int i = blockIdx.x * blockDim.x + threadIdx.x;
    if (i < e0) atomicAdd(&g_cnt0[d0[i]], 1);
    else if (i - e0 < e1) atomicAdd(&g_cnt1[d1[i - e0]], 1);
}
__global__ void scatterAll_kernel(const int* __restrict__ s0, const int* __restrict__ d0,
                                  const int* __restrict__ s1, const int* __restrict__ d1,
                                  int e0, int e1) {
    int i = blockIdx.x * blockDim.x + threadIdx.x;
    if (i < e0) {
        int p = atomicAdd(&g_cur0[d0[i]], 1);
        g_es0[p] = s0[i];
    } else if (i - e0 < e1) {
        int j = i - e0;
        int p = atomicAdd(&g_cur1[d1[j]], 1);
        g_es1[p] = s1[j];
    }
}

#define NB0 ((N1C + 511) / 512)
#define NB1 ((N2C + 511) / 512)

__device__ __forceinline__ void scan_part_impl(const int* __restrict__ cnt,
                                               int* __restrict__ part, int n, int bb) {
    __shared__ int ws[8];
    int base = bb * 512;
    int t = threadIdx.x;
    int i0 = base + t * 2;
    int s = 0;
    if (i0 < n) s += cnt[i0];
    if (i0 + 1 < n) s += cnt[i0 + 1];
    #pragma unroll
    for (int o = 16; o > 0; o >>= 1) s += __shfl_down_sync(0xffffffffu, s, o);
    if ((t & 31) == 0) ws[t >> 5] = s;
    __syncthreads();
    if (t == 0) {
        int tot = 0;
        #pragma unroll
        for (int i = 0; i < 8; i++) tot += ws[i];
        part[bb] = tot;
    }
}
__device__ __forceinline__ void scan_top_impl(int* __restrict__ part, int nb) {
    __shared__ int ws[8];
    int t = threadIdx.x;
    int v = (t < nb) ? part[t] : 0;
    int lane = t & 31, w = t >> 5;
    int incl = v;
    #pragma unroll
    for (int o = 1; o < 32; o <<= 1) {
        int x = __shfl_up_sync(0xffffffffu, incl, o);
        if (lane >= o) incl += x;
    }
    if (lane == 31) ws[w] = incl;
    __syncthreads();
    if (t == 0) {
        int run = 0;
        #pragma unroll
        for (int i = 0; i < 8; i++) { int tm = ws[i]; ws[i] = run; run += tm; }
    }
    __syncthreads();
    if (t < nb) part[t] = incl - v + ws[w];
    __syncthreads();
}
__device__ __forceinline__ void scan_final_impl(const int* __restrict__ cnt,
                                                const int* __restrict__ part,
                                                int* __restrict__ off,
                                                int* __restrict__ cur, int n, int bb) {
    __shared__ int ws[8];
    int base = bb * 512;
    int t = threadIdx.x;
    int i0 = base + t * 2;
    int c0 = (i0 < n) ? cnt[i0] : 0;
    int c1 = (i0 + 1 < n) ? cnt[i0 + 1] : 0;
    int s = c0 + c1;
    int lane = t & 31, w = t >> 5;
    int incl = s;
    #pragma unroll
    for (int o = 1; o < 32; o <<= 1) {
        int x = __shfl_up_sync(0xffffffffu, incl, o);
        if (lane >= o) incl += x;
    }
    if (lane == 31) ws[w] = incl;
    __syncthreads();
    if (t == 0) {
        int run = 0;
        #pragma unroll
        for (int i = 0; i < 8; i++) { int tm = ws[i]; ws[i] = run; run += tm; }
    }
    __syncthreads();
    int excl = incl - s + ws[w] + part[bb];
    if (i0 < n) { off[i0] = excl; cur[i0] = excl; }
    if (i0 + 1 < n) { off[i0 + 1] = excl + c0; cur[i0 + 1] = excl + c0; }
    if (i0 == n - 1) off[n] = excl + c0;
    else if (i0 + 1 == n - 1) off[n] = excl + c0 + c1;
}
__global__ void scanPart_all() {
    int b = blockIdx.x;
    if (b < NB0) scan_part_impl(g_cnt0, g_part0, N1C, b);
    else scan_part_impl(g_cnt1, g_part1, N2C, b - NB0);
}
__global__ void scanTop_all() {
    scan_top_impl(g_part0, NB0);
    scan_top_impl(g_part1, NB1);
}
__global__ void scanFinal_all() {
    int b = blockIdx.x;
    if (b < NB0) scan_final_impl(g_cnt0, g_part0, g_off0, g_cur0, N1C, b);
    else scan_final_impl(g_cnt1, g_part1, g_off1, g_cur1, N2C, b - NB0);
}

// ======================= aggregation (fp16 gather, fp32 accumulate) ===================
__device__ __forceinline__ void acc_u4(float* acc, uint4 v) {
    const __half2* h = reinterpret_cast<const __half2*>(&v);
    #pragma unroll
    for (int q = 0; q < 4; q++) {
        float2 f = __half22float2(h[q]);
        acc[q * 2 + 0] += f.x;
        acc[q * 2 + 1] += f.y;
    }
}

// one warp per dst node: gathers 512B fp16 rows from g_xc, writes g_Ac fp16
__global__ __launch_bounds__(256) void agg0_kernel() {
    int w = threadIdx.x >> 5, lane = threadIdx.x & 31;
    int d = blockIdx.x * 8 + w;
    if (d >= N1C) return;
    int b = g_off0[d], e = g_off0[d + 1];
    const uint4* xc4 = reinterpret_cast<const uint4*>(g_xc);
    float acc[8] = {};
    int i = b;
    for (; i + 1 < e; i += 2) {
        int s0 = g_es0[i], s1 = g_es0[i + 1];
        uint4 v0 = __ldg(xc4 + (size_t)s0 * 32 + lane);
        uint4 v1 = __ldg(xc4 + (size_t)s1 * 32 + lane);
        acc_u4(acc, v0);
        acc_u4(acc, v1);
    }
    if (i < e) {
        uint4 v0 = __ldg(xc4 + (size_t)g_es0[i] * 32 + lane);
        acc_u4(acc, v0);
    }
    float inv = (e > b) ? 1.f / (float)(e - b) : 0.f;
    uint4 o;
    o.x = pack2h(acc[0] * inv, acc[1] * inv);
    o.y = pack2h(acc[2] * inv, acc[3] * inv);
    o.z = pack2h(acc[4] * inv, acc[5] * inv);
    o.w = pack2h(acc[6] * inv, acc[7] * inv);
    reinterpret_cast<uint4*>(g_Ac)[(size_t)d * 32 + lane] = o;
}

// one warp per dst node: gathers 512B fp16 rows from g_X1h, writes g_Ag1h fp16
__global__ __launch_bounds__(256) void agg1_kernel() {
    int w = threadIdx.x >> 5, lane = threadIdx.x & 31;
    int d = blockIdx.x * 8 + w;
    if (d >= N2C) return;
    int b = g_off1[d], e = g_off1[d + 1];
    const uint4* x4 = reinterpret_cast<const uint4*>(g_X1h);
    float acc[8] = {};
    int i = b;
    for (; i + 1 < e; i += 2) {
        int s0 = g_es1[i], s1 = g_es1[i + 1];
        uint4 v0 = __ldg(x4 + (size_t)s0 * 32 + lane);
        uint4 v1 = __ldg(x4 + (size_t)s1 * 32 + lane);
        acc_u4(acc, v0);
        acc_u4(acc, v1);
    }
    if (i < e) {
        uint4 v0 = __ldg(x4 + (size_t)g_es1[i] * 32 + lane);
        acc_u4(acc, v0);
    }
    float inv = (e > b) ? 1.f / (float)(e - b) : 0.f;
    uint4 o;
    o.x = pack2h(acc[0] * inv, acc[1] * inv);
    o.y = pack2h(acc[2] * inv, acc[3] * inv);
    o.z = pack2h(acc[4] * inv, acc[5] * inv);
    o.w = pack2h(acc[6] * inv, acc[7] * inv);
    reinterpret_cast<uint4*>(g_Ag1h)[(size_t)d * 32 + lane] = o;
}

// ======================= HMMA fused layer-0+1 GEMM (single fp16) =====================
// X1h = relu([Ac row | xc row](K=512 fp16) @ Bh(512x256,fp16) + bias)
// CTA 128x128, 8 warps (warp tile 32x64), BK=32, double buffered; all-cp.async producer.
#define G1_A     0
#define G1_B     10240
#define G1_STAGE 20480

__global__ __launch_bounds__(256) void gemm1_mma_kernel(int M) {
    __shared__ __align__(16) char smem[2 * G1_STAGE];
    const uint32_t smem_u = smem_to_u32(smem);
    int tid = threadIdx.x;
    int lane = tid & 31, wid = tid >> 5;
    int warp_m = wid & 3, warp_n = wid >> 2;
    int rowbase = blockIdx.y * 128;
    int colbase = blockIdx.x * 128;

    int hrow = tid >> 1;            // 0..127 (A and B loaders share mapping)
    int hko = (tid & 1) * 32;       // 32B chunk

    uint32_t aoff = (uint32_t)((warp_m * 32 + (lane & 15)) * 80 + ((lane >> 4) * 16));
    uint32_t boff = (uint32_t)((warp_n * 64 + (lane & 7) + ((lane >> 4) << 3)) * 80 +
                               (((lane >> 3) & 1) * 16));

    float acc[2][8][4] = {};

    int gr = rowbase + hrow;
    if (gr >= M) gr = M - 1;

    auto cpA = [&](int s, int par) {
        const char* src = (s < 8)
            ? reinterpret_cast<const char*>(g_Ac + (size_t)gr * 256 + s * 32)
            : reinterpret_cast<const char*>(g_xc + (size_t)gr * 256 + (s - 8) * 32);
        src += hko;
        uint32_t dst = smem_u + par * G1_STAGE + G1_A + hrow * 80 + hko;
        CP_ASYNC16(dst, src);
        CP_ASYNC16(dst + 16, src + 16);
    };
    auto cpB = [&](int s, int par) {
        const char* src = reinterpret_cast<const char*>(g_Bh) +
                          (size_t)(colbase + hrow) * 1024 + (size_t)s * 64 + hko;
        uint32_t dst = smem_u + par * G1_STAGE + G1_B + hrow * 80 + hko;
        CP_ASYNC16(dst, src);
        CP_ASYNC16(dst + 16, src + 16);
    };

    cpA(0, 0);
    cpB(0, 0);
    CP_COMMIT();

    for (int s = 0; s < 16; s++) {
        int par = s & 1;
        if (s < 15) {
            cpA(s + 1, 1 - par);
            cpB(s + 1, 1 - par);
            CP_COMMIT();
            CP_WAIT(1);
        } else {
            CP_WAIT(0);
        }
        __syncthreads();

        uint32_t sb = smem_u + par * G1_STAGE;
        #pragma unroll
        for (int k16 = 0; k16 < 2; k16++) {
            uint32_t ah[8];
            LDSM4(ah,     sb + G1_A + aoff + k16 * 32);
            LDSM4(ah + 4, sb + G1_A + aoff + 16 * 80 + k16 * 32);
            uint32_t bh[16];
            #pragma unroll
            for (int nt2 = 0; nt2 < 4; nt2++)
                LDSM4(bh + nt2 * 4, sb + G1_B + boff + nt2 * 1280 + k16 * 32);
            #pragma unroll
            for (int mt = 0; mt < 2; mt++) {
                #pragma unroll
                for (int nt = 0; nt < 8; nt++)
                    MMA16816H(acc[mt][nt], ah + mt * 4, bh + nt * 2);
            }
        }
        __syncthreads();
    }

    int gid = lane >> 2, tig = lane & 3;
    #pragma unroll
    for (int nt = 0; nt < 8; nt++) {
        int col = colbase + warp_n * 64 + nt * 8 + tig * 2;
        float bb0 = g_bB[col], bb1 = g_bB[col + 1];
        float ba0 = g_bA[col], ba1 = g_bA[col + 1];
        #pragma unroll
        for (int mt = 0; mt < 2; mt++) {
            #pragma unroll
            for (int hh = 0; hh < 2; hh++) {
                int row = rowbase + warp_m * 32 + mt * 16 + gid + hh * 8;
                if (row < M) {
                    bool c = g_cnt0[row] > 0;
                    float f0 = fmaxf(acc[mt][nt][hh * 2 + 0] + bb0 + (c ? ba0 : 0.f), 0.f);
                    float f1 = fmaxf(acc[mt][nt][hh * 2 + 1] + bb1 + (c ? ba1 : 0.f), 0.f);
                    *reinterpret_cast<uint32_t*>(&g_X1h[(size_t)row * HIDF + col]) =
                        pack2h(f0, f1);
                }
            }
        }
    }
}

// ======================= layer-2 HMMA GEMM + fused log_softmax =======================
#define G2_STAGE 10240
__global__ __launch_bounds__(256) void gemm2_mma_kernel(const float* __restrict__ b2,
                                                        float* __restrict__ out, int M) {
    __shared__ __align__(16) char smem[2 * G2_STAGE];
    const uint32_t smem_u = smem_to_u32(smem);
    int tid = threadIdx.x;
    int lane = tid & 31, wid = tid >> 5;
    int rowbase = blockIdx.x * 128;

    int hrow = tid >> 1;
    int hko = (tid & 1) * 32;
    uint32_t aoff = (uint32_t)((wid * 16 + (lane & 15)) * 80 + ((lane >> 4) * 16));

    float acc[8][4] = {};

    int gr = rowbase + hrow;
    if (gr >= M) gr = M - 1;

    auto cpA = [&](int s, int par) {
        const char* src = (s < 8)
            ? reinterpret_cast<const char*>(g_Ag1h + (size_t)gr * 256 + s * 32)
            : reinterpret_cast<const char*>(g_X1h + (size_t)gr * 256 + (s - 8) * 32);
        src += hko;
        uint32_t dst = smem_u + par * G2_STAGE + hrow * 80 + hko;
        CP_ASYNC16(dst, src);
        CP_ASYNC16(dst + 16, src + 16);
    };

    cpA(0, 0);
    CP_COMMIT();
    for (int s = 0; s < 16; s++) {
        int par = s & 1;
        if (s < 15) {
            cpA(s + 1, 1 - par);
            CP_COMMIT();
            CP_WAIT(1);
        } else {
            CP_WAIT(0);
        }
        __syncthreads();
        uint32_t sb = smem_u + par * G2_STAGE;
        #pragma unroll
        for (int kk = 0; kk < 2; kk++) {
            int k16 = s * 2 + kk;
            uint32_t ah[4];
            LDSM4(ah, sb + aoff + kk * 32);
            #pragma unroll
            for (int nt = 0; nt < 8; nt++) {
                uint2 bh = __ldg(reinterpret_cast<const uint2*>(
                    g_W2f + ((size_t)(k16 * 8 + nt) * 32 + lane) * 2));
                MMA16816H(acc[nt], ah, reinterpret_cast<uint32_t*>(&bh));
            }
        }
        __syncthreads();
    }

    int gid = lane >> 2, tig = lane & 3;
    #pragma unroll
    for (int hh = 0; hh < 2; hh++) {
        int row = rowbase + wid * 16 + gid + hh * 8;
        float v[16];
        float m = -1e30f;
        #pragma unroll
        for (int nt = 0; nt < 8; nt++) {
            int col = nt * 8 + tig * 2;
            v[nt * 2 + 0] = acc[nt][hh * 2 + 0] + b2[col];
            v[nt * 2 + 1] = acc[nt][hh * 2 + 1] + b2[col + 1];
            m = fmaxf(m, fmaxf(v[nt * 2], v[nt * 2 + 1]));
        }
        m = fmaxf(m, __shfl_xor_sync(0xffffffffu, m, 1));
        m = fmaxf(m, __shfl_xor_sync(0xffffffffu, m, 2));
        float se = 0.f;
        #pragma unroll
        for (int i = 0; i < 16; i++) se += expf(v[i] - m);
        se += __shfl_xor_sync(0xffffffffu, se, 1);
        se += __shfl_xor_sync(0xffffffffu, se, 2);
        float lse = m + logf(se);
        if (row < M) {
            #pragma unroll
            for (int nt = 0; nt < 8; nt++) {
                float2 r;
                r.x = v[nt * 2 + 0] - lse;
                r.y = v[nt * 2 + 1] - lse;
                *reinterpret_cast<float2*>(&out[(size_t)row * OUTF + nt * 8 + tig * 2]) = r;
            }
        }
    }
}

// ======================= launch =======================
extern "C" void kernel_launch(void* const* d_in, const int* in_sizes, int n_in,
                              void* d_out, int out_size) {
    const float* x_tar   = (const float*)d_in[0];
    const float* x_neigh = (const float*)d_in[1];
    const int* esrc0 = (const int*)d_in[2];
    const int* edst0 = (const int*)d_in[3];
    const int* esrc1 = (const int*)d_in[4];
    const int* edst1 = (const int*)d_in[5];
    const float* Wl0 = (const float*)d_in[8];
    const float* Wr0 = (const float*)d_in[9];
    const float* b0  = (const float*)d_in[10];
    const float* Wl1 = (const float*)d_in[11];
    const float* Wr1 = (const float*)d_in[12];
    const float* b1  = (const float*)d_in[13];
    const float* Wl2 = (const float*)d_in[14];
    const float* Wr2 = (const float*)d_in[15];
    const float* b2  = (const float*)d_in[16];
    int E0 = in_sizes[2];
    int E1 = in_sizes[4];
    int M1 = N1C;
    int M2 = out_size / OUTF;
    float* out = (float*)d_out;

    zero_prep_kernel<<<ZB + WCB + W2B + 1 + CVB, 256>>>(
        x_neigh, x_tar, Wl0, Wr0, b0, Wl1, Wr1, b1, Wl2, Wr2);

    int EALL = E0 + E1;
    countAll_kernel<<<(EALL + 255) / 256, 256>>>(edst0, edst1, E0, E1);
    scanPart_all<<<NB0 + NB1, 256>>>();
    scanTop_all<<<1, 256>>>();
    scanFinal_all<<<NB0 + NB1, 256>>>();
    scatterAll_kernel<<<(EALL + 255) / 256, 256>>>(esrc0, edst0, esrc1, edst1, E0, E1);
    agg0_kernel<<<(N1C + 7) / 8, 256>>>();

    dim3 g1(2, (M1 + 127) / 128);
    gemm1_mma_kernel<<<g1, 256>>>(M1);

    agg1_kernel<<<(N2C + 7) / 8, 256>>>();
    gemm2_mma_kernel<<<(M2 + 127) / 128, 256>>>(b2, out, M2);
}